// round 1
// baseline (speedup 1.0000x reference)
#include <cuda_runtime.h>
#include <math.h>

// Problem constants
#define HEADS   16
#define DH      64
#define BATCH   2
#define SEQ     2048
#define DMODEL  1024
#define INNER   1024          // HEADS*DH
#define N3      3072          // 3*INNER
#define MROWS   (BATCH*SEQ)   // 4096

// Scratch (allocation-free rule: __device__ globals)
__device__ float g_q[BATCH*HEADS*SEQ*DH];
__device__ float g_k[BATCH*HEADS*SEQ*DH];
__device__ float g_v[BATCH*HEADS*SEQ*DH];
__device__ float g_att[MROWS*INNER];
__device__ float g_cos[SEQ*DH];
__device__ float g_sin[SEQ*DH];

// ---------------------------------------------------------------------------
// RoPE cos/sin table (computed per launch; deterministic)
// ---------------------------------------------------------------------------
__global__ void rope_table_kernel() {
    int idx = blockIdx.x * blockDim.x + threadIdx.x;
    if (idx >= SEQ * DH) return;
    int s = idx >> 6;
    int d = idx & 63;
    int f = d & 31;                        // emb = concat(freqs, freqs)
    double inv = pow(10000.0, -(double)f / 32.0);
    double th  = (double)s * inv;
    g_cos[idx] = (float)cos(th);
    g_sin[idx] = (float)sin(th);
}

// ---------------------------------------------------------------------------
// GEMM 1: qkv = x @ w_qkv, fused RoPE + head-transpose epilogue.
// C tile 64x64, BK=16, 256 threads, 4x4 per thread.
// Each 64-wide column tile is exactly one (q/k/v, head) pair.
// ---------------------------------------------------------------------------
#define BM 64
#define BN 64
#define BK 16

__global__ __launch_bounds__(256) void gemm_qkv_rope(
    const float* __restrict__ A,   // x [MROWS, DMODEL]
    const float* __restrict__ Bw)  // w_qkv [DMODEL, N3]
{
    __shared__ __align__(16) float As[BM][BK + 4];
    __shared__ __align__(16) float Bs[BK][BN];
    __shared__ float Cs[BM][BN + 1];

    const int n0  = blockIdx.x * BN;
    const int m0  = blockIdx.y * BM;
    const int tid = threadIdx.x;
    const int tx  = tid & 15;
    const int ty  = tid >> 4;

    float acc[4][4] = {};

    const int arow = tid >> 2, aq = (tid & 3) * 4;
    const int brow = tid >> 4, bq = (tid & 15) * 4;

    for (int k0 = 0; k0 < DMODEL; k0 += BK) {
        float4 va = *(const float4*)&A[(size_t)(m0 + arow) * DMODEL + k0 + aq];
        float4 vb = *(const float4*)&Bw[(size_t)(k0 + brow) * N3 + n0 + bq];
        *(float4*)&As[arow][aq] = va;
        *(float4*)&Bs[brow][bq] = vb;
        __syncthreads();

#pragma unroll
        for (int kk = 0; kk < BK; kk++) {
            float ra[4];
#pragma unroll
            for (int i = 0; i < 4; i++) ra[i] = As[ty * 4 + i][kk];
            float4 rb = *(float4*)&Bs[kk][tx * 4];
            float rbv[4] = {rb.x, rb.y, rb.z, rb.w};
#pragma unroll
            for (int i = 0; i < 4; i++)
#pragma unroll
                for (int j = 0; j < 4; j++)
                    acc[i][j] += ra[i] * rbv[j];
        }
        __syncthreads();
    }

#pragma unroll
    for (int i = 0; i < 4; i++)
#pragma unroll
        for (int j = 0; j < 4; j++)
            Cs[ty * 4 + i][tx * 4 + j] = acc[i][j];
    __syncthreads();

    // Epilogue: RoPE (q,k) or copy (v), write in [B,H,S,Dh] layout.
    const int sel = n0 / INNER;             // 0=q 1=k 2=v
    const int h   = (n0 % INNER) / DH;
    float* dst = (sel == 0) ? g_q : (sel == 1) ? g_k : g_v;

#pragma unroll
    for (int e = 0; e < 16; e++) {
        int elem = e * 256 + tid;
        int row  = elem >> 6;
        int d    = elem & 63;
        int gm   = m0 + row;
        int b    = gm / SEQ;
        int s    = gm % SEQ;
        float val;
        if (sel < 2) {
            float c  = g_cos[s * DH + d];
            float sn = g_sin[s * DH + d];
            float x1 = Cs[row][d];
            float x2 = (d < 32) ? -Cs[row][d + 32] : Cs[row][d - 32];
            val = c * x1 + sn * x2;
        } else {
            val = Cs[row][d];
        }
        dst[((size_t)(b * HEADS + h) * SEQ + s) * DH + d] = val;
    }
}

// ---------------------------------------------------------------------------
// Attention: flash-style online softmax. One block = (b,h) x 64-query tile.
// 64 threads, one query row per thread. K/V share one smem tile buffer.
// ---------------------------------------------------------------------------
__global__ __launch_bounds__(64) void attn_kernel()
{
    __shared__ __align__(16) float KV[64 * 64];     // K tile, then V tile
    __shared__ float Srow[64][65];                  // per-thread logit spill

    const int qt = blockIdx.x;          // 0..31
    const int bh = blockIdx.y;          // 0..31
    const int r  = threadIdx.x;         // 0..63
    const int s  = qt * 64 + r;

    const float* qb = g_q + (size_t)bh * SEQ * DH;
    const float* kb = g_k + (size_t)bh * SEQ * DH;
    const float* vb = g_v + (size_t)bh * SEQ * DH;

    const float scale = 0.125f;         // DH^-0.5
    float Q[64];
#pragma unroll
    for (int i = 0; i < 16; i++) {
        float4 v = *(const float4*)&qb[(size_t)s * DH + i * 4];
        Q[i*4+0] = v.x * scale; Q[i*4+1] = v.y * scale;
        Q[i*4+2] = v.z * scale; Q[i*4+3] = v.w * scale;
    }

    float O[64];
#pragma unroll
    for (int d = 0; d < 64; d++) O[d] = 0.f;
    float m = -1e30f, l = 0.f;

    float4* kvv = (float4*)KV;

    for (int kt = 0; kt < SEQ / 64; kt++) {
        __syncthreads();   // previous V tile fully consumed
        const float4* ksrc = (const float4*)&kb[(size_t)kt * 64 * DH];
#pragma unroll
        for (int i = 0; i < 16; i++) kvv[i * 64 + r] = ksrc[i * 64 + r];
        __syncthreads();

        float tmax = -1e30f;
#pragma unroll 4
        for (int j = 0; j < 64; j++) {
            const float* kr = &KV[j * 64];
            float sd = 0.f;
#pragma unroll
            for (int d = 0; d < 64; d++) sd += Q[d] * kr[d];
            Srow[r][j] = sd;
            tmax = fmaxf(tmax, sd);
        }

        float mnew = fmaxf(m, tmax);
        float corr = __expf(m - mnew);
        l *= corr;
#pragma unroll
        for (int d = 0; d < 64; d++) O[d] *= corr;
        m = mnew;

        __syncthreads();   // done reading K tile
        const float4* vsrc = (const float4*)&vb[(size_t)kt * 64 * DH];
#pragma unroll
        for (int i = 0; i < 16; i++) kvv[i * 64 + r] = vsrc[i * 64 + r];
        __syncthreads();

#pragma unroll 2
        for (int j = 0; j < 64; j++) {
            float p = __expf(Srow[r][j] - mnew);
            l += p;
            const float* vr = &KV[j * 64];
#pragma unroll
            for (int d = 0; d < 64; d++) O[d] += p * vr[d];
        }
    }

    const float inv = 1.f / l;
    const int b = bh >> 4, h = bh & 15;
    float* outp = g_att + ((size_t)(b * SEQ + s)) * INNER + h * DH;
#pragma unroll
    for (int i = 0; i < 16; i++) {
        float4 v = make_float4(O[i*4+0]*inv, O[i*4+1]*inv, O[i*4+2]*inv, O[i*4+3]*inv);
        *(float4*)&outp[i * 4] = v;
    }
}

// ---------------------------------------------------------------------------
// GEMM 2: out = g_att @ w_out  ([4096,1024] @ [1024,1024])
// ---------------------------------------------------------------------------
__global__ __launch_bounds__(256) void gemm_out(
    const float* __restrict__ Bw,   // w_out [INNER, DMODEL]
    float* __restrict__ C)          // out [MROWS, DMODEL]
{
    __shared__ __align__(16) float As[BM][BK + 4];
    __shared__ __align__(16) float Bs[BK][BN];

    const int n0  = blockIdx.x * BN;
    const int m0  = blockIdx.y * BM;
    const int tid = threadIdx.x;
    const int tx  = tid & 15;
    const int ty  = tid >> 4;

    float acc[4][4] = {};

    const int arow = tid >> 2, aq = (tid & 3) * 4;
    const int brow = tid >> 4, bq = (tid & 15) * 4;

    for (int k0 = 0; k0 < INNER; k0 += BK) {
        float4 va = *(const float4*)&g_att[(size_t)(m0 + arow) * INNER + k0 + aq];
        float4 vb = *(const float4*)&Bw[(size_t)(k0 + brow) * DMODEL + n0 + bq];
        *(float4*)&As[arow][aq] = va;
        *(float4*)&Bs[brow][bq] = vb;
        __syncthreads();

#pragma unroll
        for (int kk = 0; kk < BK; kk++) {
            float ra[4];
#pragma unroll
            for (int i = 0; i < 4; i++) ra[i] = As[ty * 4 + i][kk];
            float4 rb = *(float4*)&Bs[kk][tx * 4];
            float rbv[4] = {rb.x, rb.y, rb.z, rb.w};
#pragma unroll
            for (int i = 0; i < 4; i++)
#pragma unroll
                for (int j = 0; j < 4; j++)
                    acc[i][j] += ra[i] * rbv[j];
        }
        __syncthreads();
    }

#pragma unroll
    for (int i = 0; i < 4; i++) {
        float4 v = make_float4(acc[i][0], acc[i][1], acc[i][2], acc[i][3]);
        *(float4*)&C[(size_t)(m0 + ty * 4 + i) * DMODEL + n0 + tx * 4] = v;
    }
}

// ---------------------------------------------------------------------------
extern "C" void kernel_launch(void* const* d_in, const int* in_sizes, int n_in,
                              void* d_out, int out_size)
{
    const float* x     = (const float*)d_in[0];
    const float* w_qkv = (const float*)d_in[1];
    const float* w_out = (const float*)d_in[2];
    float* out = (float*)d_out;

    rope_table_kernel<<<(SEQ * DH + 255) / 256, 256>>>();
    gemm_qkv_rope<<<dim3(N3 / BN, MROWS / BM), 256>>>(x, w_qkv);
    attn_kernel<<<dim3(SEQ / 64, BATCH * HEADS), 64>>>();
    gemm_out<<<dim3(DMODEL / BN, MROWS / BM), 256>>>(w_out, out);
}

// round 5
// speedup vs baseline: 1.8811x; 1.8811x over previous
#include <cuda_runtime.h>
#include <mma.h>
#include <math.h>

using namespace nvcuda;

// Problem constants
#define HEADS   16
#define DH      64
#define BATCH   2
#define SEQ     2048
#define DMODEL  1024
#define INNER   1024
#define N3      3072
#define MROWS   (BATCH*SEQ)   // 4096

// Scratch
__device__ float g_q[BATCH*HEADS*SEQ*DH];
__device__ float g_k[BATCH*HEADS*SEQ*DH];
__device__ float g_v[BATCH*HEADS*SEQ*DH];
__device__ float g_att[MROWS*INNER];
__device__ float g_cos[SEQ*DH];
__device__ float g_sin[SEQ*DH];

__device__ __forceinline__ float to_tf32(float x) {
    float r;
    asm("cvt.rna.tf32.f32 %0, %1;" : "=f"(r) : "f"(x));
    return r;
}

// ---------------------------------------------------------------------------
// RoPE cos/sin table
// ---------------------------------------------------------------------------
__global__ void rope_table_kernel() {
    int idx = blockIdx.x * blockDim.x + threadIdx.x;
    if (idx >= SEQ * DH) return;
    int s = idx >> 6;
    int d = idx & 63;
    int f = d & 31;
    double inv = pow(10000.0, -(double)f / 32.0);
    double th  = (double)s * inv;
    g_cos[idx] = (float)cos(th);
    g_sin[idx] = (float)sin(th);
}

// ---------------------------------------------------------------------------
// TF32 wmma GEMM 1: qkv = x @ w_qkv, fused RoPE + head-transpose epilogue.
// Block 64x64, BK=16, 128 threads. Register-prefetch software pipeline.
// ---------------------------------------------------------------------------
#define BK 16
#define LDA 20
#define LDB 68
#define LDC 68

__global__ __launch_bounds__(128) void gemm_qkv_rope(
    const float* __restrict__ A,   // x [MROWS, DMODEL]
    const float* __restrict__ Bw)  // w_qkv [DMODEL, N3]
{
    __shared__ __align__(32) float As[64 * LDA];
    __shared__ __align__(32) float Bs[BK * LDB];
    __shared__ __align__(32) float Cs[64 * LDC];

    const int n0  = blockIdx.x * 64;
    const int m0  = blockIdx.y * 64;
    const int tid = threadIdx.x;
    const int wid = tid >> 5;
    const int wm  = (wid >> 1) * 32;
    const int wn  = (wid & 1) * 32;

    const int ar0 = tid >> 2,      ac0 = (tid & 3) * 4;
    const int ar1 = 32 + ar0;
    const int br0 = tid >> 4,      bc0 = (tid & 15) * 4;
    const int br1 = 8 + br0;

    wmma::fragment<wmma::accumulator, 16, 16, 8, float> c[2][2];
#pragma unroll
    for (int i = 0; i < 2; i++)
#pragma unroll
        for (int j = 0; j < 2; j++)
            wmma::fill_fragment(c[i][j], 0.0f);

    float4 va0 = *(const float4*)&A[(size_t)(m0 + ar0) * DMODEL + ac0];
    float4 va1 = *(const float4*)&A[(size_t)(m0 + ar1) * DMODEL + ac0];
    float4 vb0 = *(const float4*)&Bw[(size_t)br0 * N3 + n0 + bc0];
    float4 vb1 = *(const float4*)&Bw[(size_t)br1 * N3 + n0 + bc0];

    for (int k0 = 0; k0 < DMODEL; k0 += BK) {
        As[ar0 * LDA + ac0 + 0] = to_tf32(va0.x);
        As[ar0 * LDA + ac0 + 1] = to_tf32(va0.y);
        As[ar0 * LDA + ac0 + 2] = to_tf32(va0.z);
        As[ar0 * LDA + ac0 + 3] = to_tf32(va0.w);
        As[ar1 * LDA + ac0 + 0] = to_tf32(va1.x);
        As[ar1 * LDA + ac0 + 1] = to_tf32(va1.y);
        As[ar1 * LDA + ac0 + 2] = to_tf32(va1.z);
        As[ar1 * LDA + ac0 + 3] = to_tf32(va1.w);
        Bs[br0 * LDB + bc0 + 0] = to_tf32(vb0.x);
        Bs[br0 * LDB + bc0 + 1] = to_tf32(vb0.y);
        Bs[br0 * LDB + bc0 + 2] = to_tf32(vb0.z);
        Bs[br0 * LDB + bc0 + 3] = to_tf32(vb0.w);
        Bs[br1 * LDB + bc0 + 0] = to_tf32(vb1.x);
        Bs[br1 * LDB + bc0 + 1] = to_tf32(vb1.y);
        Bs[br1 * LDB + bc0 + 2] = to_tf32(vb1.z);
        Bs[br1 * LDB + bc0 + 3] = to_tf32(vb1.w);
        __syncthreads();

        int kn = k0 + BK;
        if (kn < DMODEL) {
            va0 = *(const float4*)&A[(size_t)(m0 + ar0) * DMODEL + kn + ac0];
            va1 = *(const float4*)&A[(size_t)(m0 + ar1) * DMODEL + kn + ac0];
            vb0 = *(const float4*)&Bw[(size_t)(kn + br0) * N3 + n0 + bc0];
            vb1 = *(const float4*)&Bw[(size_t)(kn + br1) * N3 + n0 + bc0];
        }

#pragma unroll
        for (int ks = 0; ks < 2; ks++) {
            wmma::fragment<wmma::matrix_a, 16, 16, 8, wmma::precision::tf32, wmma::row_major> a[2];
            wmma::fragment<wmma::matrix_b, 16, 16, 8, wmma::precision::tf32, wmma::row_major> b[2];
#pragma unroll
            for (int i = 0; i < 2; i++)
                wmma::load_matrix_sync(a[i], &As[(wm + i * 16) * LDA + ks * 8], LDA);
#pragma unroll
            for (int j = 0; j < 2; j++)
                wmma::load_matrix_sync(b[j], &Bs[(ks * 8) * LDB + wn + j * 16], LDB);
#pragma unroll
            for (int i = 0; i < 2; i++)
#pragma unroll
                for (int j = 0; j < 2; j++)
                    wmma::mma_sync(c[i][j], a[i], b[j], c[i][j]);
        }
        __syncthreads();
    }

#pragma unroll
    for (int i = 0; i < 2; i++)
#pragma unroll
        for (int j = 0; j < 2; j++)
            wmma::store_matrix_sync(&Cs[(wm + i * 16) * LDC + wn + j * 16], c[i][j],
                                    LDC, wmma::mem_row_major);
    __syncthreads();

    // Epilogue: RoPE (q,k) or copy (v), write [B,H,S,Dh]
    const int sel = n0 / INNER;
    const int h   = (n0 % INNER) / DH;
    float* dst = (sel == 0) ? g_q : (sel == 1) ? g_k : g_v;

#pragma unroll
    for (int e = 0; e < 32; e++) {
        int elem = e * 128 + tid;
        int row  = elem >> 6;
        int d    = elem & 63;
        int gm   = m0 + row;
        int b    = gm / SEQ;
        int s    = gm % SEQ;
        float val;
        if (sel < 2) {
            float cc = g_cos[s * DH + d];
            float sn = g_sin[s * DH + d];
            float x1 = Cs[row * LDC + d];
            float x2 = (d < 32) ? -Cs[row * LDC + d + 32] : Cs[row * LDC + d - 32];
            val = cc * x1 + sn * x2;
        } else {
            val = Cs[row * LDC + d];
        }
        dst[((size_t)(b * HEADS + h) * SEQ + s) * DH + d] = val;
    }
}

// ---------------------------------------------------------------------------
// Flash attention, TF32 wmma. Block = 64 queries x (b,h). 128 threads (4 warps).
// ---------------------------------------------------------------------------
#define LDS_ 68

__global__ __launch_bounds__(128) void attn_kernel()
{
    extern __shared__ __align__(32) float sm[];
    float* KVbuf = sm;                  // 64*68
    float* Sbuf  = sm + 64 * LDS_;      // 64*68
    float* Obuf  = sm + 2 * 64 * LDS_;  // 64*68

    const int qt  = blockIdx.x;
    const int bh  = blockIdx.y;
    const int tid = threadIdx.x;
    const int wid = tid >> 5;

    const float* qb = g_q + (size_t)bh * SEQ * DH + (size_t)qt * 64 * DH;
    const float* kb = g_k + (size_t)bh * SEQ * DH;
    const float* vb = g_v + (size_t)bh * SEQ * DH;

    const float scale = 0.125f;
#pragma unroll
    for (int e = 0; e < 8; e++) {
        int v = e * 128 + tid;
        int row = v >> 4, col = (v & 15) * 4;
        float4 q4 = *(const float4*)&qb[(size_t)row * DH + col];
        KVbuf[row * LDS_ + col + 0] = to_tf32(q4.x * scale);
        KVbuf[row * LDS_ + col + 1] = to_tf32(q4.y * scale);
        KVbuf[row * LDS_ + col + 2] = to_tf32(q4.z * scale);
        KVbuf[row * LDS_ + col + 3] = to_tf32(q4.w * scale);
    }
#pragma unroll
    for (int e = 0; e < 32; e++) {
        int elem = e * 128 + tid;
        Obuf[(elem >> 6) * LDS_ + (elem & 63)] = 0.0f;
    }
    __syncthreads();

    wmma::fragment<wmma::matrix_a, 16, 16, 8, wmma::precision::tf32, wmma::row_major> qf[8];
#pragma unroll
    for (int ks = 0; ks < 8; ks++)
        wmma::load_matrix_sync(qf[ks], &KVbuf[(wid * 16) * LDS_ + ks * 8], LDS_);
    __syncthreads();

    float mrow = -1e30f, lrow = 0.0f;

    for (int kt = 0; kt < SEQ / 64; kt++) {
#pragma unroll
        for (int e = 0; e < 8; e++) {
            int v = e * 128 + tid;
            int row = v >> 4, col = (v & 15) * 4;
            float4 k4 = *(const float4*)&kb[((size_t)kt * 64 + row) * DH + col];
            KVbuf[row * LDS_ + col + 0] = to_tf32(k4.x);
            KVbuf[row * LDS_ + col + 1] = to_tf32(k4.y);
            KVbuf[row * LDS_ + col + 2] = to_tf32(k4.z);
            KVbuf[row * LDS_ + col + 3] = to_tf32(k4.w);
        }
        __syncthreads();

#pragma unroll
        for (int nf = 0; nf < 4; nf++) {
            wmma::fragment<wmma::accumulator, 16, 16, 8, float> sc;
            wmma::fill_fragment(sc, 0.0f);
#pragma unroll
            for (int ks = 0; ks < 8; ks++) {
                wmma::fragment<wmma::matrix_b, 16, 16, 8, wmma::precision::tf32, wmma::col_major> bf;
                wmma::load_matrix_sync(bf, &KVbuf[(nf * 16) * LDS_ + ks * 8], LDS_);
                wmma::mma_sync(sc, qf[ks], bf, sc);
            }
            wmma::store_matrix_sync(&Sbuf[(wid * 16) * LDS_ + nf * 16], sc,
                                    LDS_, wmma::mem_row_major);
        }
        __syncthreads();

#pragma unroll
        for (int e = 0; e < 8; e++) {
            int v = e * 128 + tid;
            int row = v >> 4, col = (v & 15) * 4;
            float4 v4 = *(const float4*)&vb[((size_t)kt * 64 + row) * DH + col];
            KVbuf[row * LDS_ + col + 0] = to_tf32(v4.x);
            KVbuf[row * LDS_ + col + 1] = to_tf32(v4.y);
            KVbuf[row * LDS_ + col + 2] = to_tf32(v4.z);
            KVbuf[row * LDS_ + col + 3] = to_tf32(v4.w);
        }

        if (tid < 64) {
            float* srow = &Sbuf[tid * LDS_];
            float tmax = -1e30f;
#pragma unroll 8
            for (int j = 0; j < 64; j++) tmax = fmaxf(tmax, srow[j]);
            float mnew = fmaxf(mrow, tmax);
            float cr   = __expf(mrow - mnew);
            float psum = 0.0f;
#pragma unroll 8
            for (int j = 0; j < 64; j++) {
                float p = __expf(srow[j] - mnew);
                psum += p;
                srow[j] = to_tf32(p);
            }
            lrow = lrow * cr + psum;
            mrow = mnew;
            float* orow = &Obuf[tid * LDS_];
#pragma unroll 8
            for (int j = 0; j < 64; j++) orow[j] *= cr;
        }
        __syncthreads();

        wmma::fragment<wmma::matrix_a, 16, 16, 8, wmma::precision::tf32, wmma::row_major> pf[8];
#pragma unroll
        for (int ks = 0; ks < 8; ks++)
            wmma::load_matrix_sync(pf[ks], &Sbuf[(wid * 16) * LDS_ + ks * 8], LDS_);
#pragma unroll
        for (int nf = 0; nf < 4; nf++) {
            wmma::fragment<wmma::accumulator, 16, 16, 8, float> oc;
            wmma::load_matrix_sync(oc, &Obuf[(wid * 16) * LDS_ + nf * 16], LDS_,
                                   wmma::mem_row_major);
#pragma unroll
            for (int ks = 0; ks < 8; ks++) {
                wmma::fragment<wmma::matrix_b, 16, 16, 8, wmma::precision::tf32, wmma::row_major> vf;
                wmma::load_matrix_sync(vf, &KVbuf[(ks * 8) * LDS_ + nf * 16], LDS_);
                wmma::mma_sync(oc, pf[ks], vf, oc);
            }
            wmma::store_matrix_sync(&Obuf[(wid * 16) * LDS_ + nf * 16], oc,
                                    LDS_, wmma::mem_row_major);
        }
        __syncthreads();
    }

    if (tid < 64) {
        float inv = 1.0f / lrow;
        float* orow = &Obuf[tid * LDS_];
#pragma unroll 8
        for (int j = 0; j < 64; j++) orow[j] *= inv;
    }
    __syncthreads();

    const int b = bh >> 4, h = bh & 15;
#pragma unroll
    for (int e = 0; e < 32; e++) {
        int elem = e * 128 + tid;
        int row  = elem >> 6;
        int d    = elem & 63;
        int s    = qt * 64 + row;
        g_att[((size_t)(b * SEQ + s)) * INNER + h * DH + d] = Obuf[row * LDS_ + d];
    }
}

// ---------------------------------------------------------------------------
// TF32 wmma GEMM 2: out = g_att @ w_out  (register-prefetch pipeline)
// ---------------------------------------------------------------------------
__global__ __launch_bounds__(128) void gemm_out(
    const float* __restrict__ Bw,   // w_out [INNER, DMODEL]
    float* __restrict__ C)          // out [MROWS, DMODEL]
{
    __shared__ __align__(32) float As[64 * LDA];
    __shared__ __align__(32) float Bs[BK * LDB];

    const int n0  = blockIdx.x * 64;
    const int m0  = blockIdx.y * 64;
    const int tid = threadIdx.x;
    const int wid = tid >> 5;
    const int wm  = (wid >> 1) * 32;
    const int wn  = (wid & 1) * 32;

    const int ar0 = tid >> 2,      ac0 = (tid & 3) * 4;
    const int ar1 = 32 + ar0;
    const int br0 = tid >> 4,      bc0 = (tid & 15) * 4;
    const int br1 = 8 + br0;

    wmma::fragment<wmma::accumulator, 16, 16, 8, float> c[2][2];
#pragma unroll
    for (int i = 0; i < 2; i++)
#pragma unroll
        for (int j = 0; j < 2; j++)
            wmma::fill_fragment(c[i][j], 0.0f);

    float4 va0 = *(const float4*)&g_att[(size_t)(m0 + ar0) * INNER + ac0];
    float4 va1 = *(const float4*)&g_att[(size_t)(m0 + ar1) * INNER + ac0];
    float4 vb0 = *(const float4*)&Bw[(size_t)br0 * DMODEL + n0 + bc0];
    float4 vb1 = *(const float4*)&Bw[(size_t)br1 * DMODEL + n0 + bc0];

    for (int k0 = 0; k0 < INNER; k0 += BK) {
        As[ar0 * LDA + ac0 + 0] = to_tf32(va0.x);
        As[ar0 * LDA + ac0 + 1] = to_tf32(va0.y);
        As[ar0 * LDA + ac0 + 2] = to_tf32(va0.z);
        As[ar0 * LDA + ac0 + 3] = to_tf32(va0.w);
        As[ar1 * LDA + ac0 + 0] = to_tf32(va1.x);
        As[ar1 * LDA + ac0 + 1] = to_tf32(va1.y);
        As[ar1 * LDA + ac0 + 2] = to_tf32(va1.z);
        As[ar1 * LDA + ac0 + 3] = to_tf32(va1.w);
        Bs[br0 * LDB + bc0 + 0] = to_tf32(vb0.x);
        Bs[br0 * LDB + bc0 + 1] = to_tf32(vb0.y);
        Bs[br0 * LDB + bc0 + 2] = to_tf32(vb0.z);
        Bs[br0 * LDB + bc0 + 3] = to_tf32(vb0.w);
        Bs[br1 * LDB + bc0 + 0] = to_tf32(vb1.x);
        Bs[br1 * LDB + bc0 + 1] = to_tf32(vb1.y);
        Bs[br1 * LDB + bc0 + 2] = to_tf32(vb1.z);
        Bs[br1 * LDB + bc0 + 3] = to_tf32(vb1.w);
        __syncthreads();

        int kn = k0 + BK;
        if (kn < INNER) {
            va0 = *(const float4*)&g_att[(size_t)(m0 + ar0) * INNER + kn + ac0];
            va1 = *(const float4*)&g_att[(size_t)(m0 + ar1) * INNER + kn + ac0];
            vb0 = *(const float4*)&Bw[(size_t)(kn + br0) * DMODEL + n0 + bc0];
            vb1 = *(const float4*)&Bw[(size_t)(kn + br1) * DMODEL + n0 + bc0];
        }

#pragma unroll
        for (int ks = 0; ks < 2; ks++) {
            wmma::fragment<wmma::matrix_a, 16, 16, 8, wmma::precision::tf32, wmma::row_major> a[2];
            wmma::fragment<wmma::matrix_b, 16, 16, 8, wmma::precision::tf32, wmma::row_major> b[2];
#pragma unroll
            for (int i = 0; i < 2; i++)
                wmma::load_matrix_sync(a[i], &As[(wm + i * 16) * LDA + ks * 8], LDA);
#pragma unroll
            for (int j = 0; j < 2; j++)
                wmma::load_matrix_sync(b[j], &Bs[(ks * 8) * LDB + wn + j * 16], LDB);
#pragma unroll
            for (int i = 0; i < 2; i++)
#pragma unroll
                for (int j = 0; j < 2; j++)
                    wmma::mma_sync(c[i][j], a[i], b[j], c[i][j]);
        }
        __syncthreads();
    }

#pragma unroll
    for (int i = 0; i < 2; i++)
#pragma unroll
        for (int j = 0; j < 2; j++)
            wmma::store_matrix_sync(&C[(size_t)(m0 + wm + i * 16) * DMODEL + n0 + wn + j * 16],
                                    c[i][j], DMODEL, wmma::mem_row_major);
}

// ---------------------------------------------------------------------------
extern "C" void kernel_launch(void* const* d_in, const int* in_sizes, int n_in,
                              void* d_out, int out_size)
{
    const float* x     = (const float*)d_in[0];
    const float* w_qkv = (const float*)d_in[1];
    const float* w_out = (const float*)d_in[2];
    float* out = (float*)d_out;

    cudaFuncSetAttribute(attn_kernel,
                         cudaFuncAttributeMaxDynamicSharedMemorySize,
                         3 * 64 * LDS_ * sizeof(float));

    rope_table_kernel<<<(SEQ * DH + 255) / 256, 256>>>();
    gemm_qkv_rope<<<dim3(N3 / 64, MROWS / 64), 128>>>(x, w_qkv);
    attn_kernel<<<dim3(SEQ / 64, BATCH * HEADS), 128,
                  3 * 64 * LDS_ * sizeof(float)>>>();
    gemm_out<<<dim3(DMODEL / 64, MROWS / 64), 128>>>(w_out, out);
}